// round 14
// baseline (speedup 1.0000x reference)
#include <cuda_runtime.h>
#include <cuda_bf16.h>
#include <cstdint>

// Indexer gather: out[i, :] = items[min((int)(clamp(indices[i],0,1)*1024), 1023), :]
// indices: [1048576] f32, items: [1024, 256] f32, out: [1048576, 256] f32.
//
// R9 = R8 (best: 142.6us, ~94% of HBM write spec) with 128-thread CTAs.
// Same per-thread pattern: one output row's 4 float4 chunks at cols
// (tid&15)+16i -> one L1-broadcast index load, 4 independent L2-hit gathers
// (1 MB items table fully L2-resident), 4 __stcs streaming stores.
// Halved CTA granularity (131072 CTAs, 16 CTA/SM x 128 thr = same 2048
// resident threads/SM) -> finer work-stealing, smaller straggler tail at
// wave boundaries. Warp-level coalescing identical (pattern is a 16-lane-
// group property).
// Refuted levers: deeper MLP (R3), persistent grid (R5), index pairing (R6),
// default store policy (R7). DRAM traffic == mandatory writes only.

static constexpr int N_INDICES   = 1048576;
static constexpr int D_ITEM      = 256;
static constexpr int N_ITEMS     = 1024;
static constexpr int VEC_PER_ROW = D_ITEM / 4;                                  // 64
static constexpr int ITERS   = 4;
static constexpr int THREADS = 128;
static constexpr long long TOTAL_THREADS = (long long)N_INDICES * (VEC_PER_ROW / ITERS); // 2^24

__global__ __launch_bounds__(THREADS, 16)
void indexer_gather_kernel(const float* __restrict__ indices,
                           const float4* __restrict__ items,
                           float4* __restrict__ out)
{
    unsigned tid = blockIdx.x * blockDim.x + threadIdx.x;   // < 2^24
    unsigned row = tid >> 4;          // output/index row   (< 2^20)
    unsigned c0  = tid & 15u;         // base float4 column

    // One index load per thread (broadcast within each 16-lane group).
    float x = __ldg(&indices[row]);
    x = fminf(fmaxf(x, 0.0f), 1.0f) * (float)N_ITEMS;     // x in [0, 1024]
    int closest = min((int)x, N_ITEMS - 1);               // trunc == floor (x >= 0)
    const float4* irow = items + (unsigned)closest * VEC_PER_ROW;

    float4 val[ITERS];
    #pragma unroll
    for (int i = 0; i < ITERS; i++) {
        val[i] = __ldg(&irow[c0 + 16u * i]);     // 4 independent L2-hit gathers
    }

    float4* orow = out + (unsigned long long)row * VEC_PER_ROW;
    #pragma unroll
    for (int i = 0; i < ITERS; i++) {
        __stcs(&orow[c0 + 16u * i], val[i]);     // streaming stores, fully coalesced
    }
}

extern "C" void kernel_launch(void* const* d_in, const int* in_sizes, int n_in,
                              void* d_out, int out_size)
{
    const float*  indices = (const float*)d_in[0];
    const float4* items   = (const float4*)d_in[1];
    float4*       out     = (float4*)d_out;

    const unsigned blocks = (unsigned)(TOTAL_THREADS / THREADS);   // 131072
    indexer_gather_kernel<<<blocks, THREADS>>>(indices, items, out);
}

// round 17
// speedup vs baseline: 1.0025x; 1.0025x over previous
#include <cuda_runtime.h>
#include <cuda_bf16.h>
#include <cstdint>

// Indexer gather: out[i, :] = items[min((int)(clamp(indices[i],0,1)*1024), 1023), :]
// indices: [1048576] f32, items: [1024, 256] f32, out: [1048576, 256] f32.
//
// R10 FINAL — locked R8 config (best measured: 142.6us = 7.53 TB/s of
// mandatory output writes, ~94% of the 8 TB/s HBM spec; DRAM traffic is
// writes-only, items table fully L2-absorbed).
//
// Per thread: one output row's 4 float4 chunks at cols (tid&15)+16i:
//   1x L1-broadcast index load -> clamp/trunc -> 4 independent L2-hit
//   gathers (MLP=4) -> 4 __stcs streaming stores (fully coalesced).
// 65536 straight-line CTAs of 256 threads, 28 regs, occ 8.
//
// Design-space ledger:
//   WIN   MLP 1->4 per thread (R2), same-row layout w/ 1 idx load (R4),
//         trunc-cast cleanup (R8)
//   FAIL  MLP=8 (R3: 48 regs, occ collapse), persistent grid-stride
//         (R5: serializes stream), default-policy stores (R7)
//   NEUT  paired-row idx hiding (R6), 128-thr CTAs (R9)

static constexpr int N_INDICES   = 1048576;
static constexpr int D_ITEM      = 256;
static constexpr int N_ITEMS     = 1024;
static constexpr int VEC_PER_ROW = D_ITEM / 4;                                  // 64
static constexpr int ITERS   = 4;
static constexpr int THREADS = 256;
static constexpr long long TOTAL_THREADS = (long long)N_INDICES * (VEC_PER_ROW / ITERS); // 2^24

__global__ __launch_bounds__(THREADS, 8)
void indexer_gather_kernel(const float* __restrict__ indices,
                           const float4* __restrict__ items,
                           float4* __restrict__ out)
{
    unsigned tid = blockIdx.x * blockDim.x + threadIdx.x;   // < 2^24
    unsigned row = tid >> 4;          // output/index row   (< 2^20)
    unsigned c0  = tid & 15u;         // base float4 column

    // One index load per thread (broadcast within each 16-lane group).
    float x = __ldg(&indices[row]);
    x = fminf(fmaxf(x, 0.0f), 1.0f) * (float)N_ITEMS;     // x in [0, 1024]
    int closest = min((int)x, N_ITEMS - 1);               // trunc == floor (x >= 0)
    const float4* irow = items + (unsigned)closest * VEC_PER_ROW;

    float4 val[ITERS];
    #pragma unroll
    for (int i = 0; i < ITERS; i++) {
        val[i] = __ldg(&irow[c0 + 16u * i]);     // 4 independent L2-hit gathers
    }

    float4* orow = out + (unsigned long long)row * VEC_PER_ROW;
    #pragma unroll
    for (int i = 0; i < ITERS; i++) {
        __stcs(&orow[c0 + 16u * i], val[i]);     // streaming stores, fully coalesced
    }
}

extern "C" void kernel_launch(void* const* d_in, const int* in_sizes, int n_in,
                              void* d_out, int out_size)
{
    const float*  indices = (const float*)d_in[0];
    const float4* items   = (const float4*)d_in[1];
    float4*       out     = (float4*)d_out;

    const unsigned blocks = (unsigned)(TOTAL_THREADS / THREADS);   // 65536
    indexer_gather_kernel<<<blocks, THREADS>>>(indices, items, out);
}